// round 10
// baseline (speedup 1.0000x reference)
#include <cuda_runtime.h>
#include <cstdint>

// Problem shape (fixed by the reference): x [B=2, T=256, N=1024, C=256] fp32
//   out[b,t,n,c] = g*shifted + (1-g)*x,  g = sigmoid(sum_s' ... )  (see reference)
// GEMM view per batch: Y[s, j] = sum_t W[s,t] * X[t, j],  X = x[b] as [256, 262144] row-major.

constexpr int T_DIM  = 256;     // time = M = K
constexpr int NCOLS  = 262144;  // N*C per batch
constexpr int BATCH  = 2;
constexpr int CTILE  = 128;     // columns per CTA
constexpr int KCHUNK = 32;      // K streamed in chunks of 32
constexpr int NKC    = T_DIM / KCHUNK;   // 8 chunks
constexpr int XSTR   = 136;     // X smem row stride (floats) -> conflict-free B frags
constexpr int WSTR   = 36;      // W smem row stride (floats) -> conflict-free A frags

// SMEM (floats): Xs[256][136] + Ws[2][256][36] + bias[256]
constexpr int SMEM_FLOATS = T_DIM * XSTR + 2 * T_DIM * WSTR + T_DIM;
constexpr int SMEM_BYTES  = SMEM_FLOATS * 4;   // 214016 B

__device__ __forceinline__ void cp16(void* s, const void* g) {
    uint32_t sa = (uint32_t)__cvta_generic_to_shared(s);
    asm volatile("cp.async.cg.shared.global [%0], [%1], 16;" :: "r"(sa), "l"(g));
}
__device__ __forceinline__ uint32_t f2tf(float f) {
    uint32_t r;
    asm("cvt.rna.tf32.f32 %0, %1;" : "=r"(r) : "f"(f));
    return r;
}
__device__ __forceinline__ void mma_tf32(float* d, const uint32_t* a, const uint32_t* b) {
    asm volatile(
        "mma.sync.aligned.m16n8k8.row.col.f32.tf32.tf32.f32 "
        "{%0,%1,%2,%3}, {%4,%5,%6,%7}, {%8,%9}, {%0,%1,%2,%3};"
        : "+f"(d[0]), "+f"(d[1]), "+f"(d[2]), "+f"(d[3])
        : "r"(a[0]), "r"(a[1]), "r"(a[2]), "r"(a[3]), "r"(b[0]), "r"(b[1]));
}

__global__ void __launch_bounds__(256, 1)
tokengsm_kernel(const float* __restrict__ x, const float* __restrict__ Wg,
                const float* __restrict__ bias, float* __restrict__ out)
{
    extern __shared__ float smem[];
    float* Xs  = smem;                       // [256][136]
    float* Wsm = smem + T_DIM * XSTR;        // [2][256][36]
    float* bs  = Wsm + 2 * T_DIM * WSTR;     // [256]

    const int tid   = threadIdx.x;
    const int ct    = blockIdx.x;
    const int batch = ct >> 11;                    // 2048 column tiles per batch
    const int j0    = (ct & 2047) * CTILE;
    const float* xb = x   + (size_t)batch * T_DIM * NCOLS;
    float*       ob = out + (size_t)batch * T_DIM * NCOLS;

    bs[tid] = bias[tid];   // 256 threads, 256 entries

    // ---- async staging of one K chunk (X rows + W columns) ----
    auto submit_chunk = [&](int kc) {
        const int buf = kc & 1;
        // X chunk: 32 rows x 128 floats = 1024 x 16B segs
        #pragma unroll
        for (int i = 0; i < 4; ++i) {
            int idx = tid + i * 256;
            int r = idx >> 5, seg = idx & 31;
            const float* g = xb + (size_t)(kc * KCHUNK + r) * NCOLS + j0 + seg * 4;
            cp16(Xs + (kc * KCHUNK + r) * XSTR + seg * 4, g);
        }
        // W chunk: 256 rows x 32 floats = 2048 x 16B segs
        #pragma unroll
        for (int i = 0; i < 8; ++i) {
            int idx = tid + i * 256;
            int s = idx >> 3, seg = idx & 7;
            const float* g = Wg + (size_t)s * T_DIM + kc * KCHUNK + seg * 4;
            cp16(Wsm + buf * T_DIM * WSTR + s * WSTR + seg * 4, g);
        }
        asm volatile("cp.async.commit_group;" ::: "memory");
    };

    submit_chunk(0);
    submit_chunk(1);

    const int wid  = tid >> 5, lane = tid & 31;
    const int wm   = wid >> 1;            // 0..3 : M block of 64 rows
    const int wn   = wid & 1;             // 0..1 : N block of 64 cols
    const int gid  = lane >> 2;           // 0..7
    const int tig  = lane & 3;            // 0..3

    float d[4][8][4];
    #pragma unroll
    for (int mt = 0; mt < 4; ++mt)
        #pragma unroll
        for (int nt = 0; nt < 8; ++nt)
            #pragma unroll
            for (int r = 0; r < 4; ++r) d[mt][nt][r] = 0.f;

    for (int kc = 0; kc < NKC; ++kc) {
        if (kc < NKC - 1) asm volatile("cp.async.wait_group 1;" ::: "memory");
        else              asm volatile("cp.async.wait_group 0;" ::: "memory");
        __syncthreads();

        const float* Wc = Wsm + (kc & 1) * T_DIM * WSTR;
        #pragma unroll
        for (int ks = 0; ks < 4; ++ks) {
            const int kk = kc * KCHUNK + ks * 8;
            uint32_t a[4][4], b[8][2];
            #pragma unroll
            for (int mt = 0; mt < 4; ++mt) {
                const float* w0 = Wc + (wm * 64 + mt * 16 + gid) * WSTR + ks * 8 + tig;
                a[mt][0] = f2tf(w0[0]);
                a[mt][2] = f2tf(w0[4]);
                a[mt][1] = f2tf(w0[8 * WSTR]);
                a[mt][3] = f2tf(w0[8 * WSTR + 4]);
            }
            #pragma unroll
            for (int nt = 0; nt < 8; ++nt) {
                const float* xp = Xs + (kk + tig) * XSTR + wn * 64 + nt * 8 + gid;
                b[nt][0] = f2tf(xp[0]);
                b[nt][1] = f2tf(xp[4 * XSTR]);
            }
            #pragma unroll
            for (int mt = 0; mt < 4; ++mt)
                #pragma unroll
                for (int nt = 0; nt < 8; ++nt)
                    mma_tf32(d[mt][nt], a[mt], b[nt]);
        }
        __syncthreads();
        if (kc + 2 < NKC) submit_chunk(kc + 2);
    }

    // ---- fused epilogue: gate + channel-sliced temporal shift ----
    // c = (j0+col) & 255 ; c<64: shifted = x[t-1] ; 64<=c<128: x[t+1] ; else x[t]
    #pragma unroll
    for (int mt = 0; mt < 4; ++mt) {
        const int s0 = wm * 64 + mt * 16 + gid;
        #pragma unroll
        for (int nt = 0; nt < 8; ++nt) {
            const int col = wn * 64 + nt * 8 + tig * 2;
            const int cc  = ((j0 + col) >> 6) & 3;   // uniform within 8-col ntile
            #pragma unroll
            for (int h = 0; h < 2; ++h) {
                const int s = s0 + h * 8;
                const float bb = bs[s];
                const float z0 = d[mt][nt][h * 2 + 0] + bb;
                const float z1 = d[mt][nt][h * 2 + 1] + bb;
                const float g0 = __fdividef(1.f, 1.f + __expf(-z0));
                const float g1 = __fdividef(1.f, 1.f + __expf(-z1));
                const float2 xc = *(const float2*)(Xs + s * XSTR + col);
                float2 xs;
                if (cc == 0) {
                    xs = (s == 0) ? make_float2(0.f, 0.f)
                                  : *(const float2*)(Xs + (s - 1) * XSTR + col);
                } else if (cc == 1) {
                    xs = (s == T_DIM - 1) ? make_float2(0.f, 0.f)
                                          : *(const float2*)(Xs + (s + 1) * XSTR + col);
                } else {
                    xs = xc;
                }
                float2 ov;
                ov.x = fmaf(g0, xs.x - xc.x, xc.x);
                ov.y = fmaf(g1, xs.y - xc.y, xc.y);
                *(float2*)(ob + (size_t)s * NCOLS + j0 + col) = ov;
            }
        }
    }
}

extern "C" void kernel_launch(void* const* d_in, const int* in_sizes, int n_in,
                              void* d_out, int out_size)
{
    const float* x = (const float*)d_in[0];   // [2,256,1024,256] fp32
    const float* W = (const float*)d_in[1];   // [256,256]
    const float* b = (const float*)d_in[2];   // [256]
    float* out = (float*)d_out;

    cudaFuncSetAttribute(tokengsm_kernel,
                         cudaFuncAttributeMaxDynamicSharedMemorySize, SMEM_BYTES);

    const int grid = BATCH * (NCOLS / CTILE);   // 4096 CTAs
    tokengsm_kernel<<<grid, 256, SMEM_BYTES>>>(x, W, b, out);
}

// round 11
// speedup vs baseline: 1.0015x; 1.0015x over previous
#include <cuda_runtime.h>
#include <cstdint>

// Problem shape (fixed by the reference): x [B=2, T=256, N=1024, C=256] fp32
//   out[b,t,n,c] = g*shifted + (1-g)*x,  g = sigmoid(sum_s' ... )  (see reference)
// GEMM view per batch: Y[s, j] = sum_t W[s,t] * X[t, j],  X = x[b] as [256, 262144] row-major.

constexpr int T_DIM  = 256;     // time = M = K
constexpr int NCOLS  = 262144;  // N*C per batch
constexpr int BATCH  = 2;
constexpr int CTILE  = 128;     // columns per CTA
constexpr int KCHUNK = 32;      // K streamed in chunks of 32
constexpr int NKC    = T_DIM / KCHUNK;   // 8 chunks
constexpr int XSTR   = 136;     // X smem row stride (floats) -> conflict-free B frags
constexpr int WSTR   = 36;      // W smem row stride (floats) -> conflict-free A frags

// SMEM (floats): Xs[256][136] + Ws[2][256][36] + bias[256]
constexpr int SMEM_FLOATS = T_DIM * XSTR + 2 * T_DIM * WSTR + T_DIM;
constexpr int SMEM_BYTES  = SMEM_FLOATS * 4;   // 214016 B

__device__ __forceinline__ void cp16(void* s, const void* g) {
    uint32_t sa = (uint32_t)__cvta_generic_to_shared(s);
    asm volatile("cp.async.cg.shared.global [%0], [%1], 16;" :: "r"(sa), "l"(g));
}
__device__ __forceinline__ uint32_t f2tf(float f) {
    uint32_t r;
    asm("cvt.rna.tf32.f32 %0, %1;" : "=r"(r) : "f"(f));
    return r;
}
__device__ __forceinline__ void mma_tf32(float* d, const uint32_t* a, const uint32_t* b) {
    asm volatile(
        "mma.sync.aligned.m16n8k8.row.col.f32.tf32.tf32.f32 "
        "{%0,%1,%2,%3}, {%4,%5,%6,%7}, {%8,%9}, {%0,%1,%2,%3};"
        : "+f"(d[0]), "+f"(d[1]), "+f"(d[2]), "+f"(d[3])
        : "r"(a[0]), "r"(a[1]), "r"(a[2]), "r"(a[3]), "r"(b[0]), "r"(b[1]));
}

__global__ void __launch_bounds__(256, 1)
tokengsm_kernel(const float* __restrict__ x, const float* __restrict__ Wg,
                const float* __restrict__ bias, float* __restrict__ out)
{
    extern __shared__ float smem[];
    float* Xs  = smem;                       // [256][136]
    float* Wsm = smem + T_DIM * XSTR;        // [2][256][36]
    float* bs  = Wsm + 2 * T_DIM * WSTR;     // [256]

    const int tid   = threadIdx.x;
    const int ct    = blockIdx.x;
    const int batch = ct >> 11;                    // 2048 column tiles per batch
    const int j0    = (ct & 2047) * CTILE;
    const float* xb = x   + (size_t)batch * T_DIM * NCOLS;
    float*       ob = out + (size_t)batch * T_DIM * NCOLS;

    bs[tid] = bias[tid];   // 256 threads, 256 entries

    // ---- async staging of one K chunk (X rows + W columns) ----
    auto submit_chunk = [&](int kc) {
        const int buf = kc & 1;
        // X chunk: 32 rows x 128 floats = 1024 x 16B segs
        #pragma unroll
        for (int i = 0; i < 4; ++i) {
            int idx = tid + i * 256;
            int r = idx >> 5, seg = idx & 31;
            const float* g = xb + (size_t)(kc * KCHUNK + r) * NCOLS + j0 + seg * 4;
            cp16(Xs + (kc * KCHUNK + r) * XSTR + seg * 4, g);
        }
        // W chunk: 256 rows x 32 floats = 2048 x 16B segs
        #pragma unroll
        for (int i = 0; i < 8; ++i) {
            int idx = tid + i * 256;
            int s = idx >> 3, seg = idx & 7;
            const float* g = Wg + (size_t)s * T_DIM + kc * KCHUNK + seg * 4;
            cp16(Wsm + buf * T_DIM * WSTR + s * WSTR + seg * 4, g);
        }
        asm volatile("cp.async.commit_group;" ::: "memory");
    };

    submit_chunk(0);
    submit_chunk(1);

    const int wid  = tid >> 5, lane = tid & 31;
    const int wm   = wid >> 1;            // 0..3 : M block of 64 rows
    const int wn   = wid & 1;             // 0..1 : N block of 64 cols
    const int gid  = lane >> 2;           // 0..7
    const int tig  = lane & 3;            // 0..3

    float d[4][8][4];
    #pragma unroll
    for (int mt = 0; mt < 4; ++mt)
        #pragma unroll
        for (int nt = 0; nt < 8; ++nt)
            #pragma unroll
            for (int r = 0; r < 4; ++r) d[mt][nt][r] = 0.f;

    for (int kc = 0; kc < NKC; ++kc) {
        if (kc < NKC - 1) asm volatile("cp.async.wait_group 1;" ::: "memory");
        else              asm volatile("cp.async.wait_group 0;" ::: "memory");
        __syncthreads();

        const float* Wc = Wsm + (kc & 1) * T_DIM * WSTR;
        #pragma unroll
        for (int ks = 0; ks < 4; ++ks) {
            const int kk = kc * KCHUNK + ks * 8;
            uint32_t a[4][4], b[8][2];
            #pragma unroll
            for (int mt = 0; mt < 4; ++mt) {
                const float* w0 = Wc + (wm * 64 + mt * 16 + gid) * WSTR + ks * 8 + tig;
                a[mt][0] = f2tf(w0[0]);
                a[mt][2] = f2tf(w0[4]);
                a[mt][1] = f2tf(w0[8 * WSTR]);
                a[mt][3] = f2tf(w0[8 * WSTR + 4]);
            }
            #pragma unroll
            for (int nt = 0; nt < 8; ++nt) {
                const float* xp = Xs + (kk + tig) * XSTR + wn * 64 + nt * 8 + gid;
                b[nt][0] = f2tf(xp[0]);
                b[nt][1] = f2tf(xp[4 * XSTR]);
            }
            #pragma unroll
            for (int mt = 0; mt < 4; ++mt)
                #pragma unroll
                for (int nt = 0; nt < 8; ++nt)
                    mma_tf32(d[mt][nt], a[mt], b[nt]);
        }
        __syncthreads();
        if (kc + 2 < NKC) submit_chunk(kc + 2);
    }

    // ---- fused epilogue: gate + channel-sliced temporal shift ----
    // c = (j0+col) & 255 ; c<64: shifted = x[t-1] ; 64<=c<128: x[t+1] ; else x[t]
    #pragma unroll
    for (int mt = 0; mt < 4; ++mt) {
        const int s0 = wm * 64 + mt * 16 + gid;
        #pragma unroll
        for (int nt = 0; nt < 8; ++nt) {
            const int col = wn * 64 + nt * 8 + tig * 2;
            const int cc  = ((j0 + col) >> 6) & 3;   // uniform within 8-col ntile
            #pragma unroll
            for (int h = 0; h < 2; ++h) {
                const int s = s0 + h * 8;
                const float bb = bs[s];
                const float z0 = d[mt][nt][h * 2 + 0] + bb;
                const float z1 = d[mt][nt][h * 2 + 1] + bb;
                const float g0 = __fdividef(1.f, 1.f + __expf(-z0));
                const float g1 = __fdividef(1.f, 1.f + __expf(-z1));
                const float2 xc = *(const float2*)(Xs + s * XSTR + col);
                float2 xs;
                if (cc == 0) {
                    xs = (s == 0) ? make_float2(0.f, 0.f)
                                  : *(const float2*)(Xs + (s - 1) * XSTR + col);
                } else if (cc == 1) {
                    xs = (s == T_DIM - 1) ? make_float2(0.f, 0.f)
                                          : *(const float2*)(Xs + (s + 1) * XSTR + col);
                } else {
                    xs = xc;
                }
                float2 ov;
                ov.x = fmaf(g0, xs.x - xc.x, xc.x);
                ov.y = fmaf(g1, xs.y - xc.y, xc.y);
                *(float2*)(ob + (size_t)s * NCOLS + j0 + col) = ov;
            }
        }
    }
}

extern "C" void kernel_launch(void* const* d_in, const int* in_sizes, int n_in,
                              void* d_out, int out_size)
{
    const float* x = (const float*)d_in[0];   // [2,256,1024,256] fp32
    const float* W = (const float*)d_in[1];   // [256,256]
    const float* b = (const float*)d_in[2];   // [256]
    float* out = (float*)d_out;

    cudaFuncSetAttribute(tokengsm_kernel,
                         cudaFuncAttributeMaxDynamicSharedMemorySize, SMEM_BYTES);

    const int grid = BATCH * (NCOLS / CTILE);   // 4096 CTAs
    tokengsm_kernel<<<grid, 256, SMEM_BYTES>>>(x, W, b, out);
}

// round 12
// speedup vs baseline: 1.1469x; 1.1452x over previous
#include <cuda_runtime.h>
#include <cstdint>

// x [B=2, T=256, N=1024, C=256] fp32.  GEMM per batch: Y[s,j] = sum_t W[s,t] X[t,j],
// fused with sigmoid gate + channel-sliced temporal shift epilogue.

constexpr int T_DIM  = 256;     // time = M = K
constexpr int NCOLS  = 262144;  // N*C per batch
constexpr int BATCH  = 2;
constexpr int CTILE  = 128;     // columns per CTA
constexpr int KCHUNK = 32;      // K streamed in chunks of 32
constexpr int NKC    = T_DIM / KCHUNK;   // 8 chunks
constexpr int XSTR   = 136;     // X smem row stride (floats) -> conflict-free B frags

// Fragment-packed W: [kc(8)][ks(4)][wm(4)][mt(4)][lane(32)][4 floats] = 65536 floats
__device__ float Wpk_g[T_DIM * T_DIM];

// SMEM (floats): Xs[256][136] + Wfrag[2][8192] + bias[256]
constexpr int WFRAG_CHUNK = 8192;       // floats per K-chunk of packed W
constexpr int SMEM_FLOATS = T_DIM * XSTR + 2 * WFRAG_CHUNK + T_DIM;
constexpr int SMEM_BYTES  = SMEM_FLOATS * 4;   // 205,824 B

__device__ __forceinline__ void cp16(void* s, const void* g) {
    uint32_t sa = (uint32_t)__cvta_generic_to_shared(s);
    asm volatile("cp.async.cg.shared.global [%0], [%1], 16;" :: "r"(sa), "l"(g));
}
__device__ __forceinline__ uint32_t f2tf(float f) {
    uint32_t r;
    asm("cvt.rna.tf32.f32 %0, %1;" : "=r"(r) : "f"(f));
    return r;
}
__device__ __forceinline__ void mma_tf32(float* d, const uint32_t* a, const uint32_t* b) {
    asm volatile(
        "mma.sync.aligned.m16n8k8.row.col.f32.tf32.tf32.f32 "
        "{%0,%1,%2,%3}, {%4,%5,%6,%7}, {%8,%9}, {%0,%1,%2,%3};"
        : "+f"(d[0]), "+f"(d[1]), "+f"(d[2]), "+f"(d[3])
        : "r"(a[0]), "r"(a[1]), "r"(a[2]), "r"(a[3]), "r"(b[0]), "r"(b[1]));
}

// Prologue: repack W into per-lane MMA A-fragments, TF32-rounded (rna).
// Fragment for lane(gid,tig), tile (wm,mt,kc,ks):
//   { W[r][c], W[r+8][c], W[r][c+4], W[r+8][c+4] },
//   r = wm*64 + mt*16 + gid,  c = kc*32 + ks*8 + tig.
__global__ void repack_W_kernel(const float* __restrict__ W)
{
    const int idx  = blockIdx.x * 256 + threadIdx.x;   // float4 index, 0..16383
    const int lane = idx & 31;
    const int mt   = (idx >> 5) & 3;
    const int wm   = (idx >> 7) & 3;
    const int ks   = (idx >> 9) & 3;
    const int kc   = idx >> 11;
    const int gid  = lane >> 2, tig = lane & 3;
    const int r = wm * 64 + mt * 16 + gid;
    const int c = kc * 32 + ks * 8 + tig;
    uint4 u;
    u.x = f2tf(W[(size_t)r * T_DIM + c]);
    u.y = f2tf(W[(size_t)(r + 8) * T_DIM + c]);
    u.z = f2tf(W[(size_t)r * T_DIM + c + 4]);
    u.w = f2tf(W[(size_t)(r + 8) * T_DIM + c + 4]);
    reinterpret_cast<uint4*>(Wpk_g)[idx] = u;
}

__global__ void __launch_bounds__(256, 1)
tokengsm_kernel(const float* __restrict__ x, const float* __restrict__ bias,
                float* __restrict__ out)
{
    extern __shared__ float smem[];
    float* Xs = smem;                        // [256][136]
    float* Wb = smem + T_DIM * XSTR;         // [2][8192] fragment-packed
    float* bs = Wb + 2 * WFRAG_CHUNK;        // [256]

    const int tid   = threadIdx.x;
    const int ct    = blockIdx.x;
    const int batch = ct >> 11;                    // 2048 column tiles per batch
    const int j0    = (ct & 2047) * CTILE;
    const float* xb = x   + (size_t)batch * T_DIM * NCOLS;
    float*       ob = out + (size_t)batch * T_DIM * NCOLS;

    bs[tid] = bias[tid];

    // ---- async staging of one K chunk (X rows + packed W fragments) ----
    auto submit_chunk = [&](int kc) {
        const int buf = kc & 1;
        // X chunk: 32 rows x 128 floats = 1024 x 16B segs
        #pragma unroll
        for (int i = 0; i < 4; ++i) {
            int idx = tid + i * 256;
            int r = idx >> 5, seg = idx & 31;
            const float* g = xb + (size_t)(kc * KCHUNK + r) * NCOLS + j0 + seg * 4;
            cp16(Xs + (kc * KCHUNK + r) * XSTR + seg * 4, g);
        }
        // Packed W chunk: 8192 floats = 2048 x 16B segs
        #pragma unroll
        for (int i = 0; i < 8; ++i) {
            int idx = tid + i * 256;
            cp16(Wb + buf * WFRAG_CHUNK + idx * 4, Wpk_g + kc * WFRAG_CHUNK + idx * 4);
        }
        asm volatile("cp.async.commit_group;" ::: "memory");
    };

    submit_chunk(0);
    submit_chunk(1);

    const int wid  = tid >> 5, lane = tid & 31;
    const int wm   = wid >> 1;            // 0..3 : M block of 64 rows
    const int wn   = wid & 1;             // 0..1 : N block of 64 cols
    const int gid  = lane >> 2;           // 0..7
    const int tig  = lane & 3;            // 0..3

    float d[4][8][4];
    #pragma unroll
    for (int mt = 0; mt < 4; ++mt)
        #pragma unroll
        for (int nt = 0; nt < 8; ++nt)
            #pragma unroll
            for (int r = 0; r < 4; ++r) d[mt][nt][r] = 0.f;

    for (int kc = 0; kc < NKC; ++kc) {
        if (kc < NKC - 1) asm volatile("cp.async.wait_group 1;" ::: "memory");
        else              asm volatile("cp.async.wait_group 0;" ::: "memory");
        __syncthreads();

        const float* Wc = Wb + (kc & 1) * WFRAG_CHUNK + wm * 512 + lane * 4;
        #pragma unroll
        for (int ks = 0; ks < 4; ++ks) {
            const int kk = kc * KCHUNK + ks * 8;
            // A fragments: one LDS.128 per m-tile (pre-rounded tf32 bits)
            uint32_t a[4][4];
            #pragma unroll
            for (int mt = 0; mt < 4; ++mt) {
                uint4 v = *reinterpret_cast<const uint4*>(Wc + ks * 2048 + mt * 128);
                a[mt][0] = v.x; a[mt][1] = v.y; a[mt][2] = v.z; a[mt][3] = v.w;
            }
            // B fragments: raw fp32 bits (HW truncates to tf32)
            uint32_t b[8][2];
            const uint32_t* xr0 = reinterpret_cast<const uint32_t*>(
                Xs + (size_t)(kk + tig) * XSTR + wn * 64 + gid);
            const uint32_t* xr1 = xr0 + 4 * XSTR;
            #pragma unroll
            for (int nt = 0; nt < 8; ++nt) {
                b[nt][0] = xr0[nt * 8];
                b[nt][1] = xr1[nt * 8];
            }
            #pragma unroll
            for (int mt = 0; mt < 4; ++mt)
                #pragma unroll
                for (int nt = 0; nt < 8; ++nt)
                    mma_tf32(d[mt][nt], a[mt], b[nt]);
        }
        __syncthreads();
        if (kc + 2 < NKC) submit_chunk(kc + 2);
    }

    // ---- fused epilogue: gate + channel-sliced temporal shift ----
    // c = (j0+col) & 255 ; c<64: shifted = x[t-1] ; 64<=c<128: x[t+1] ; else x[t]
    #pragma unroll
    for (int mt = 0; mt < 4; ++mt) {
        const int s0 = wm * 64 + mt * 16 + gid;
        #pragma unroll
        for (int nt = 0; nt < 8; ++nt) {
            const int col = wn * 64 + nt * 8 + tig * 2;
            const int cc  = ((j0 + col) >> 6) & 3;   // uniform within 8-col ntile
            #pragma unroll
            for (int h = 0; h < 2; ++h) {
                const int s = s0 + h * 8;
                const float bb = bs[s];
                const float z0 = d[mt][nt][h * 2 + 0] + bb;
                const float z1 = d[mt][nt][h * 2 + 1] + bb;
                const float g0 = __fdividef(1.f, 1.f + __expf(-z0));
                const float g1 = __fdividef(1.f, 1.f + __expf(-z1));
                const float2 xc = *(const float2*)(Xs + (size_t)s * XSTR + col);
                float2 xs;
                if (cc == 0) {
                    xs = (s == 0) ? make_float2(0.f, 0.f)
                                  : *(const float2*)(Xs + (size_t)(s - 1) * XSTR + col);
                } else if (cc == 1) {
                    xs = (s == T_DIM - 1) ? make_float2(0.f, 0.f)
                                          : *(const float2*)(Xs + (size_t)(s + 1) * XSTR + col);
                } else {
                    xs = xc;
                }
                float2 ov;
                ov.x = fmaf(g0, xs.x - xc.x, xc.x);
                ov.y = fmaf(g1, xs.y - xc.y, xc.y);
                *(float2*)(ob + (size_t)s * NCOLS + j0 + col) = ov;
            }
        }
    }
}

extern "C" void kernel_launch(void* const* d_in, const int* in_sizes, int n_in,
                              void* d_out, int out_size)
{
    const float* x = (const float*)d_in[0];   // [2,256,1024,256] fp32
    const float* W = (const float*)d_in[1];   // [256,256]
    const float* b = (const float*)d_in[2];   // [256]
    float* out = (float*)d_out;

    repack_W_kernel<<<64, 256>>>(W);

    cudaFuncSetAttribute(tokengsm_kernel,
                         cudaFuncAttributeMaxDynamicSharedMemorySize, SMEM_BYTES);
    const int grid = BATCH * (NCOLS / CTILE);   // 4096 CTAs
    tokengsm_kernel<<<grid, 256, SMEM_BYTES>>>(x, b, out);
}